// round 2
// baseline (speedup 1.0000x reference)
#include <cuda_runtime.h>
#include <cuda_bf16.h>

// Global double accumulator (no device mallocs allowed).
__device__ double g_acc;

__global__ void zero_acc_kernel() {
    if (threadIdx.x == 0 && blockIdx.x == 0) g_acc = 0.0;
}

// 4 threads per row; each thread handles 16 consecutive floats (4x float4).
// D = 64 fixed.
__global__ __launch_bounds__(256) void mahal_main_kernel(
    const float4* __restrict__ yt,
    const float4* __restrict__ yp,
    const float*  __restrict__ param,
    const int*    __restrict__ n)
{
    const int tid = blockIdx.x * blockDim.x + threadIdx.x;
    const int row = tid >> 2;        // B rows, grid sized exactly
    const int lin = tid & 3;         // quarter-row index 0..3

    const int nv = __ldg(&n[row]);

    // coef from param (scalar, cached in L1/const path)
    const float pm = __ldg(&param[0]);
    const float p  = 2.0f / (1.0f + __expf(-pm)) - 1.0f;
    const float coef = -p / (1.0f + p * p);

    // base float4 index: 16 float4 per row
    const int base = row * 16 + lin * 4;
    const int tbase = lin * 16;      // column of first element this thread owns

    float d[16];
#pragma unroll
    for (int i = 0; i < 4; i++) {
        const float4 a = __ldg(&yt[base + i]);
        const float4 b = __ldg(&yp[base + i]);
        const int t0 = tbase + i * 4;
        d[4 * i + 0] = (t0 + 0 < nv) ? (a.x - b.x) : 0.0f;
        d[4 * i + 1] = (t0 + 1 < nv) ? (a.y - b.y) : 0.0f;
        d[4 * i + 2] = (t0 + 2 < nv) ? (a.z - b.z) : 0.0f;
        d[4 * i + 3] = (t0 + 3 < nv) ? (a.w - b.w) : 0.0f;
    }

    float sumsq = 0.0f, sumadj = 0.0f;
#pragma unroll
    for (int k = 0; k < 16; k++) sumsq = fmaf(d[k], d[k], sumsq);
#pragma unroll
    for (int k = 0; k < 15; k++) sumadj = fmaf(d[k], d[k + 1], sumadj);

    // cross-segment adjacent product: my last * neighbor's first
    const float nfirst = __shfl_down_sync(0xffffffffu, d[0], 1);
    if (lin < 3) sumadj = fmaf(d[15], nfirst, sumadj);

    float quad = fmaf(2.0f * coef, sumadj, sumsq);

    // reduce the 4 lanes of this row (valid at lin==0)
    quad += __shfl_down_sync(0xffffffffu, quad, 1);
    quad += __shfl_down_sync(0xffffffffu, quad, 2);

    float v = (lin == 0) ? quad / (float)nv : 0.0f;

    // full-warp reduction (8 row values live in the warp)
#pragma unroll
    for (int off = 16; off > 0; off >>= 1)
        v += __shfl_xor_sync(0xffffffffu, v, off);

    __shared__ float warp_sums[8];
    const int warp = threadIdx.x >> 5;
    const int lane = threadIdx.x & 31;
    if (lane == 0) warp_sums[warp] = v;
    __syncthreads();

    if (warp == 0) {
        float bs = (lane < 8) ? warp_sums[lane] : 0.0f;
#pragma unroll
        for (int off = 4; off > 0; off >>= 1)
            bs += __shfl_xor_sync(0xffffffffu, bs, off);
        if (lane == 0)
            atomicAdd(&g_acc, (double)bs);
    }
}

__global__ void finalize_kernel(float* __restrict__ out, int B) {
    if (threadIdx.x == 0 && blockIdx.x == 0)
        out[0] = (float)(g_acc / (double)B);
}

extern "C" void kernel_launch(void* const* d_in, const int* in_sizes, int n_in,
                              void* d_out, int out_size) {
    const float4* yt    = (const float4*)d_in[0];  // y_true  (B, 64) fp32
    const float4* yp    = (const float4*)d_in[1];  // y_pred  (B, 64) fp32
    const float*  param = (const float*)d_in[2];   // (1,)
    const int*    n     = (const int*)d_in[3];     // (B,)
    float* out = (float*)d_out;

    const int B = in_sizes[3];                     // element count of n == batch
    const int threads = 256;
    const long long total = (long long)B * 4;      // 4 threads / row
    const int blocks = (int)((total + threads - 1) / threads);

    zero_acc_kernel<<<1, 32>>>();
    mahal_main_kernel<<<blocks, threads>>>(yt, yp, param, n);
    finalize_kernel<<<1, 32>>>(out, B);
}